// round 8
// baseline (speedup 1.0000x reference)
#include <cuda_runtime.h>

#define DIM 192
#define SMOOTH_DR 1e-5f
#define N_TOTAL (2.0 * 192.0 * 192.0 * 192.0)

#define BXT 16              // threads in x, each covers 4 x -> 64 x per block
#define BYT 16              // output rows per block (every thread is an output thread)
#define ZCHUNK 48
#define GX 3                // 3 * 64 = 192
#define GY 12               // 12 * 16 = 192
#define GZ 8                // 2 batches * 4 z-chunks
#define NBLK (GX * GY * GZ) // 288

typedef unsigned long long u64;

__device__ double g_acc = 0.0;
__device__ unsigned int g_count = 0u;

// ---- packed f32x2 helpers (sm_103a) ----
__device__ __forceinline__ u64 pk2(float lo, float hi) {
    u64 r; asm("mov.b64 %0, {%1, %2};" : "=l"(r) : "f"(lo), "f"(hi)); return r;
}
__device__ __forceinline__ void upk2(u64 v, float& lo, float& hi) {
    asm("mov.b64 {%0, %1}, %2;" : "=f"(lo), "=f"(hi) : "l"(v));
}
__device__ __forceinline__ u64 f2add(u64 a, u64 b) {
    u64 d; asm("add.rn.f32x2 %0, %1, %2;" : "=l"(d) : "l"(a), "l"(b)); return d;
}
__device__ __forceinline__ u64 f2mul(u64 a, u64 b) {
    u64 d; asm("mul.rn.f32x2 %0, %1, %2;" : "=l"(d) : "l"(a), "l"(b)); return d;
}
__device__ __forceinline__ u64 f2fma(u64 a, u64 b, u64 c) {
    u64 d; asm("fma.rn.f32x2 %0, %1, %2, %3;" : "=l"(d) : "l"(a), "l"(b), "l"(c)); return d;
}

// Five overlapping pairs covering elements e0..e5 of a 6-wide strip:
// A={e0,e1} L={e1,e2} M={e2,e3} H={e3,e4} B={e4,e5}
// window sums: lo = A+L+M = {e0+e1+e2, e1+e2+e3}, hi = M+H+B = {e2+e3+e4, e3+e4+e5}
struct Packs { u64 A, L, M, H, B; };

__device__ __forceinline__ Packs load_packs(const float* __restrict__ row,
                                            bool valid, int x0, int tx)
{
    float4 v = make_float4(0.f, 0.f, 0.f, 0.f);
    if (valid) v = __ldg((const float4*)(row + x0));
    // x-1 from lane-1's e4 (v.w), x+4 from lane+1's e1 (v.x); 16-lane segments
    float e0 = __shfl_up_sync(0xffffffffu, v.w, 1, 16);
    float e5 = __shfl_down_sync(0xffffffffu, v.x, 1, 16);
    if (tx == 0)       e0 = (valid && x0 > 0)       ? __ldg(row + x0 - 1) : 0.f;
    if (tx == BXT - 1) e5 = (valid && x0 + 4 < DIM) ? __ldg(row + x0 + 4) : 0.f;
    Packs P;
    P.A = pk2(e0,  v.x);
    P.L = pk2(v.x, v.y);
    P.M = pk2(v.y, v.z);
    P.H = pk2(v.z, v.w);
    P.B = pk2(v.w, e5);
    return P;
}

__global__ void __launch_bounds__(BXT * BYT)
ncc_kernel(const float* __restrict__ pred, const float* __restrict__ targ,
           float* __restrict__ out)
{
    const int tx = threadIdx.x;
    const int ty = threadIdx.y;
    const int x0 = (blockIdx.x * BXT + tx) * 4;   // < 192 always
    const int y  = blockIdx.y * BYT + ty;         // < 192 always
    const int zb = blockIdx.z;
    const int b  = zb >> 2;                       // batch
    const int zc = (zb & 3) * ZCHUNK;             // chunk base plane

    const float* pbase = pred + (size_t)b * DIM * DIM * DIM;
    const float* tbase = targ + (size_t)b * DIM * DIM * DIM;

    const u64 NEGC = pk2(-1.f / 27.f, -1.f / 27.f);
    const u64 DRP  = pk2(SMOOTH_DR, SMOOTH_DR);

    // z-ring: 3 plane-slots x 10 packs
    // [0]=I_lo [1]=I_hi [2]=J_lo [3]=J_hi [4]=II_lo [5]=II_hi
    // [6]=JJ_lo [7]=JJ_hi [8]=IJ_lo [9]=IJ_hi
    u64 ring[3][10];
    float acc = 0.f;

    // sweep planes zp = zc-2 .. zc+ZCHUNK (ZCHUNK+3 = 51 iterations)
    for (int itc = 0; itc < (ZCHUNK + 3) / 3; ++itc) {
#pragma unroll
        for (int sub = 0; sub < 3; ++sub) {
            const int it = itc * 3 + sub;
            const int zp = zc - 2 + it;
            const bool zok = (zp >= 0) && (zp < DIM);

            u64* xy = ring[sub];   // static index under unroll -> registers

#pragma unroll
            for (int r = 0; r < 3; ++r) {
                const int yr = y - 1 + r;
                const bool ok = zok && (yr >= 0) && (yr < DIM);
                const size_t off = ((size_t)zp * DIM + yr) * DIM;
                Packs P = load_packs(pbase + off, ok, x0, tx);
                Packs T = load_packs(tbase + off, ok, x0, tx);

                // linear window sums
                u64 Ilo = f2add(f2add(P.A, P.L), P.M);
                u64 Ihi = f2add(f2add(P.M, P.H), P.B);
                u64 Jlo = f2add(f2add(T.A, T.L), T.M);
                u64 Jhi = f2add(f2add(T.M, T.H), T.B);
                // squared / cross products, then their window sums
                u64 pA = f2mul(P.A, P.A), pL = f2mul(P.L, P.L), pM = f2mul(P.M, P.M),
                    pH = f2mul(P.H, P.H), pB = f2mul(P.B, P.B);
                u64 IIlo = f2add(f2add(pA, pL), pM);
                u64 IIhi = f2add(f2add(pM, pH), pB);
                u64 qA = f2mul(T.A, T.A), qL = f2mul(T.L, T.L), qM = f2mul(T.M, T.M),
                    qH = f2mul(T.H, T.H), qB = f2mul(T.B, T.B);
                u64 JJlo = f2add(f2add(qA, qL), qM);
                u64 JJhi = f2add(f2add(qM, qH), qB);
                u64 cA = f2mul(P.A, T.A), cL = f2mul(P.L, T.L), cM = f2mul(P.M, T.M),
                    cH = f2mul(P.H, T.H), cB = f2mul(P.B, T.B);
                u64 IJlo = f2add(f2add(cA, cL), cM);
                u64 IJhi = f2add(f2add(cM, cH), cB);

                if (r == 0) {
                    xy[0] = Ilo;  xy[1] = Ihi;  xy[2] = Jlo;  xy[3] = Jhi;
                    xy[4] = IIlo; xy[5] = IIhi; xy[6] = JJlo; xy[7] = JJhi;
                    xy[8] = IJlo; xy[9] = IJhi;
                } else {
                    xy[0] = f2add(xy[0], Ilo);  xy[1] = f2add(xy[1], Ihi);
                    xy[2] = f2add(xy[2], Jlo);  xy[3] = f2add(xy[3], Jhi);
                    xy[4] = f2add(xy[4], IIlo); xy[5] = f2add(xy[5], IIhi);
                    xy[6] = f2add(xy[6], JJlo); xy[7] = f2add(xy[7], JJhi);
                    xy[8] = f2add(xy[8], IJlo); xy[9] = f2add(xy[9], IJhi);
                }
            }

            if (it >= 3) {   // output plane z = zp - 1 (uniform across block)
                u64 zs[10];
#pragma unroll
                for (int k = 0; k < 10; ++k)
                    zs[k] = f2add(f2add(ring[0][k], ring[1][k]), ring[2][k]);

                // cross = SIJ - SI*SJ/27 ; pvar = SII - SI^2/27 ; tvar = SJJ - SJ^2/27
                u64 SImlo = f2mul(zs[0], NEGC), SImhi = f2mul(zs[1], NEGC);
                u64 SJmlo = f2mul(zs[2], NEGC), SJmhi = f2mul(zs[3], NEGC);
                u64 crlo = f2fma(SImlo, zs[2], zs[8]);
                u64 crhi = f2fma(SImhi, zs[3], zs[9]);
                u64 pvlo = f2fma(SImlo, zs[0], zs[4]);
                u64 pvhi = f2fma(SImhi, zs[1], zs[5]);
                u64 tvlo = f2fma(SJmlo, zs[2], zs[6]);
                u64 tvhi = f2fma(SJmhi, zs[3], zs[7]);
                u64 nmlo = f2mul(crlo, crlo), nmhi = f2mul(crhi, crhi);
                u64 dnlo = f2fma(tvlo, pvlo, DRP), dnhi = f2fma(tvhi, pvhi, DRP);

                float n0, n1, n2, n3, d0, d1, d2, d3;
                upk2(nmlo, n0, n1); upk2(nmhi, n2, n3);
                upk2(dnlo, d0, d1); upk2(dnhi, d2, d3);
                acc += __fdividef(n0, d0) + __fdividef(n1, d1)
                     + __fdividef(n2, d2) + __fdividef(n3, d3);
            }
        }
    }

    // ---- block reduction + fused finalize ----
    __shared__ float red[BXT * BYT];
    const int tid = ty * BXT + tx;
    red[tid] = acc;
    __syncthreads();
#pragma unroll
    for (int s = (BXT * BYT) / 2; s > 0; s >>= 1) {
        if (tid < s) red[tid] += red[tid + s];
        __syncthreads();
    }
    if (tid == 0) {
        atomicAdd(&g_acc, (double)red[0]);
        __threadfence();
        unsigned t = atomicAdd(&g_count, 1u);
        if (t == NBLK - 1) {           // last block: finalize + reset for replay
            double total = *((volatile double*)&g_acc);
            out[0] = (float)(-total / N_TOTAL);
            g_acc = 0.0;
            g_count = 0u;
        }
    }
}

extern "C" void kernel_launch(void* const* d_in, const int* in_sizes, int n_in,
                              void* d_out, int out_size) {
    const float* pred = (const float*)d_in[0];
    const float* targ = (const float*)d_in[1];
    float* out = (float*)d_out;

    dim3 block(BXT, BYT);
    dim3 grid(GX, GY, GZ);
    ncc_kernel<<<grid, block>>>(pred, targ, out);
}

// round 10
// speedup vs baseline: 1.9729x; 1.9729x over previous
#include <cuda_runtime.h>

#define DIM 192
#define SMOOTH_DR 1e-5f
#define N_TOTAL (2.0 * 192.0 * 192.0 * 192.0)

#define BXT 16              // threads in x; each covers 2 x -> 32 x per block
#define BYT 18              // 16 output rows + 2 halo producer rows
#define NTHR (BXT * BYT)    // 288
#define ZCHUNK 24
#define GX 6                // 6 * 32 = 192
#define GY 12               // 12 * 16 = 192
#define GZ 16               // 2 batches * 8 z-chunks
#define NBLK (GX * GY * GZ) // 1152

typedef unsigned long long u64;

__device__ double g_acc = 0.0;
__device__ unsigned int g_count = 0u;

// ---- packed f32x2 helpers (sm_103a) ----
__device__ __forceinline__ u64 pk2(float lo, float hi) {
    u64 r; asm("mov.b64 %0, {%1, %2};" : "=l"(r) : "f"(lo), "f"(hi)); return r;
}
__device__ __forceinline__ void upk2(u64 v, float& lo, float& hi) {
    asm("mov.b64 {%0, %1}, %2;" : "=f"(lo), "=f"(hi) : "l"(v));
}
__device__ __forceinline__ u64 f2add(u64 a, u64 b) {
    u64 d; asm("add.rn.f32x2 %0, %1, %2;" : "=l"(d) : "l"(a), "l"(b)); return d;
}
__device__ __forceinline__ u64 f2mul(u64 a, u64 b) {
    u64 d; asm("mul.rn.f32x2 %0, %1, %2;" : "=l"(d) : "l"(a), "l"(b)); return d;
}
__device__ __forceinline__ u64 f2fma(u64 a, u64 b, u64 c) {
    u64 d; asm("fma.rn.f32x2 %0, %1, %2, %3;" : "=l"(d) : "l"(a), "l"(b), "l"(c)); return d;
}

__global__ void __launch_bounds__(NTHR, 3)
ncc_kernel(const float* __restrict__ pred, const float* __restrict__ targ,
           float* __restrict__ out)
{
    // double-buffered zx-sums: [parity][quantity][row][tx]
    __shared__ u64 s[2][5][BYT][BXT];

    const int tx = threadIdx.x;
    const int ty = threadIdx.y;
    const int x0 = (blockIdx.x * BXT + tx) * 2;       // 0..190
    const int yp = blockIdx.y * 16 + ty - 1;          // produced row: -1..192
    const int zb = blockIdx.z;
    const int b  = zb >> 3;
    const int zc = (zb & 7) * ZCHUNK;

    const bool yok = (yp >= 0) && (yp < DIM);
    const bool lx = (tx == 0);
    const bool rx = (tx == BXT - 1);

    const float* pb = pred + (size_t)b * DIM * DIM * DIM;
    const float* tb = targ + (size_t)b * DIM * DIM * DIM;

    const u64 NEGC = pk2(-1.f / 27.f, -1.f / 27.f);
    const u64 DRP  = pk2(SMOOTH_DR, SMOOTH_DR);

    // rolling z-window state: A = xs(prev plane), P = xs(prev-2)+xs(prev)
    u64 rA[5], rP[5];
#pragma unroll
    for (int q = 0; q < 5; ++q) { rA[q] = 0ull; rP[q] = 0ull; }

    float acc = 0.f;

    // prefetch registers for next plane
    u64 vP, vT; float eP0, eP3, eT0, eT3;

    auto load_plane = [&](int zp, u64& VP, u64& VT,
                          float& EP0, float& EP3, float& ET0, float& ET3) {
        const bool ok = (zp >= 0) && (zp < DIM) && yok;
        const size_t off = ((size_t)zp * DIM + yp) * DIM + x0;
        float2 p = make_float2(0.f, 0.f), t = make_float2(0.f, 0.f);
        if (ok) {
            p = __ldg((const float2*)(pb + off));
            t = __ldg((const float2*)(tb + off));
        }
        VP = pk2(p.x, p.y);
        VT = pk2(t.x, t.y);
        EP0 = 0.f; EP3 = 0.f; ET0 = 0.f; ET3 = 0.f;
        if (lx && ok && x0 > 0) {
            EP0 = __ldg(pb + off - 1);  ET0 = __ldg(tb + off - 1);
        }
        if (rx && ok && x0 + 2 < DIM) {
            EP3 = __ldg(pb + off + 2);  ET3 = __ldg(tb + off + 2);
        }
    };

    // planes zp = zc-2 .. zc+24 (27 iterations); output center z = zc-3+it for it in [3,26]
    load_plane(zc - 2, vP, vT, eP0, eP3, eT0, eT3);

    for (int it = 0; it <= 26; ++it) {
        // latch current plane, prefetch next
        const u64 cP = vP, cT = vT;
        const float cP0 = eP0, cP3 = eP3, cT0 = eT0, cT3 = eT3;
        if (it < 26) load_plane(zc - 1 + it, vP, vT, eP0, eP3, eT0, eT3);

        // ---- x-window sums for this (plane, row): 5 packs ----
        float p1, p2, t1, t2;
        upk2(cP, p1, p2); upk2(cT, t1, t2);
        float p0 = __shfl_up_sync(0xffffffffu, p2, 1, 16);
        float p3 = __shfl_down_sync(0xffffffffu, p1, 1, 16);
        float t0 = __shfl_up_sync(0xffffffffu, t2, 1, 16);
        float t3 = __shfl_down_sync(0xffffffffu, t1, 1, 16);
        if (lx) { p0 = cP0; t0 = cT0; }
        if (rx) { p3 = cP3; t3 = cT3; }

        const u64 A = pk2(p0, p1), M = cP, B = pk2(p2, p3);
        const u64 C = pk2(t0, t1), N = cT, D = pk2(t2, t3);

        u64 xs[5];
        xs[0] = f2add(f2add(A, M), B);                    // sum I
        xs[1] = f2add(f2add(C, N), D);                    // sum J
        xs[2] = f2fma(A, A, f2fma(M, M, f2mul(B, B)));    // sum I*I
        xs[3] = f2fma(C, C, f2fma(N, N, f2mul(D, D)));    // sum J*J
        xs[4] = f2fma(A, C, f2fma(M, N, f2mul(B, D)));    // sum I*J

        // ---- rolling z-sum: zs = rP + xs; advance window ----
        u64 zs[5];
#pragma unroll
        for (int q = 0; q < 5; ++q) {
            zs[q] = f2add(rP[q], xs[q]);
            rP[q] = f2add(rA[q], xs[q]);
            rA[q] = xs[q];
        }

        if (it >= 3) {   // block-uniform
            const int pbuf = it & 1;
#pragma unroll
            for (int q = 0; q < 5; ++q) s[pbuf][q][ty][tx] = zs[q];
            __syncthreads();

            if (ty >= 1 && ty <= 16) {
                u64 S[5];
#pragma unroll
                for (int q = 0; q < 5; ++q)
                    S[q] = f2add(zs[q],
                                 f2add(s[pbuf][q][ty - 1][tx], s[pbuf][q][ty + 1][tx]));

                // cross = SIJ - SI*SJ/27 ; pvar = SII - SI^2/27 ; tvar = SJJ - SJ^2/27
                const u64 SIm = f2mul(S[0], NEGC);
                const u64 SJm = f2mul(S[1], NEGC);
                const u64 cr  = f2fma(SIm, S[1], S[4]);
                const u64 pv  = f2fma(SIm, S[0], S[2]);
                const u64 tv  = f2fma(SJm, S[1], S[3]);
                const u64 num = f2mul(cr, cr);
                const u64 den = f2fma(tv, pv, DRP);

                float n0, n1, d0, d1;
                upk2(num, n0, n1); upk2(den, d0, d1);
                acc += __fdividef(n0, d0) + __fdividef(n1, d1);
            }
        }
    }

    // ---- block reduction + fused finalize ----
    // warp reduce (all 32 lanes alive)
#pragma unroll
    for (int o = 16; o > 0; o >>= 1)
        acc += __shfl_down_sync(0xffffffffu, acc, o);

    __syncthreads();                      // done with stencil smem reads
    float* wsum = (float*)&s[0][0][0][0]; // reuse smem
    const int tid = ty * BXT + tx;
    const int wid = tid >> 5;             // 9 warps
    if ((tid & 31) == 0) wsum[wid] = acc;
    __syncthreads();

    if (tid == 0) {
        float blocksum = 0.f;
#pragma unroll
        for (int w = 0; w < NTHR / 32; ++w) blocksum += wsum[w];
        atomicAdd(&g_acc, (double)blocksum);
        __threadfence();
        unsigned t = atomicAdd(&g_count, 1u);
        if (t == NBLK - 1) {              // last block: finalize + reset for replay
            double total = *((volatile double*)&g_acc);
            out[0] = (float)(-total / N_TOTAL);
            g_acc = 0.0;
            g_count = 0u;
        }
    }
}

extern "C" void kernel_launch(void* const* d_in, const int* in_sizes, int n_in,
                              void* d_out, int out_size) {
    const float* pred = (const float*)d_in[0];
    const float* targ = (const float*)d_in[1];
    float* out = (float*)d_out;

    dim3 block(BXT, BYT);
    dim3 grid(GX, GY, GZ);
    ncc_kernel<<<grid, block>>>(pred, targ, out);
}

// round 11
// speedup vs baseline: 2.0990x; 1.0639x over previous
#include <cuda_runtime.h>

#define DIM 192
#define PLANE (DIM * DIM)
#define SMOOTH_DR 1e-5f
#define N_TOTAL (2.0 * 192.0 * 192.0 * 192.0)

#define BXT 32              // threads in x; each covers 2 x -> 64 x per block
#define BYT 9               // threads in y; each owns 2 adjacent rows (18 rows: 16 out + 2 halo)
#define NTHR (BXT * BYT)    // 288
#define ZCHUNK 24
#define GX 3                // 3 * 64 = 192
#define GY 12               // 12 * 16 = 192
#define GZ 16               // 2 batches * 8 z-chunks
#define NBLK (GX * GY * GZ) // 576

typedef unsigned long long u64;

__device__ double g_acc = 0.0;
__device__ unsigned int g_count = 0u;

// ---- packed f32x2 helpers (sm_103a) ----
__device__ __forceinline__ u64 pk2(float lo, float hi) {
    u64 r; asm("mov.b64 %0, {%1, %2};" : "=l"(r) : "f"(lo), "f"(hi)); return r;
}
__device__ __forceinline__ void upk2(u64 v, float& lo, float& hi) {
    asm("mov.b64 {%0, %1}, %2;" : "=f"(lo), "=f"(hi) : "l"(v));
}
__device__ __forceinline__ u64 f2add(u64 a, u64 b) {
    u64 d; asm("add.rn.f32x2 %0, %1, %2;" : "=l"(d) : "l"(a), "l"(b)); return d;
}
__device__ __forceinline__ u64 f2mul(u64 a, u64 b) {
    u64 d; asm("mul.rn.f32x2 %0, %1, %2;" : "=l"(d) : "l"(a), "l"(b)); return d;
}
__device__ __forceinline__ u64 f2fma(u64 a, u64 b, u64 c) {
    u64 d; asm("fma.rn.f32x2 %0, %1, %2, %3;" : "=l"(d) : "l"(a), "l"(b), "l"(c)); return d;
}

__global__ void __launch_bounds__(NTHR, 2)
ncc_kernel(const float* __restrict__ pred, const float* __restrict__ targ,
           float* __restrict__ out)
{
    // double-buffered zx-sums: [parity][quantity][rowsel a/b][ty][tx]
    __shared__ u64 s[2][5][2][BYT][BXT];

    const int tx = threadIdx.x;
    const int ty = threadIdx.y;
    const int x0 = blockIdx.x * 64 + tx * 2;        // 0..190
    const int ya = blockIdx.y * 16 + 2 * ty - 1;    // row a: -1 .. 191
    const int zb = blockIdx.z;
    const int b  = zb >> 3;
    const int zc = (zb & 7) * ZCHUNK;

    const bool yok[2] = { (ya >= 0), (ya + 1 < DIM) };   // ya <= 191 always
    const bool lx = (tx == 0), rx = (tx == BXT - 1);
    const bool hasL = lx && (blockIdx.x > 0);
    const bool hasR = rx && (blockIdx.x < GX - 1);

    const float* pb = pred + b * (DIM * DIM * DIM);
    const float* tb = targ + b * (DIM * DIM * DIM);

    const u64 NEGC = pk2(-1.f / 27.f, -1.f / 27.f);
    const u64 DRP  = pk2(SMOOTH_DR, SMOOTH_DR);

    // z-ring per owned row: A = xs(prev plane), P = xs(prev-2)+xs(prev)
    u64 rA[2][5], rP[2][5];
#pragma unroll
    for (int r = 0; r < 2; ++r)
#pragma unroll
        for (int q = 0; q < 5; ++q) { rA[r][q] = 0ull; rP[r][q] = 0ull; }

    float acc = 0.f;

    // int element offsets (volume < 2^23 elems); advance by PLANE per z
    int off[2];
    off[0] = (zc - 2) * PLANE + ya * DIM + x0;
    off[1] = off[0] + DIM;
    int zp = zc - 2;

    // prefetch state per row: packed I,J + 4 edge scalars
    u64 nP[2], nT[2];
    float nE[2][4];

    auto load_row = [&](int r, bool zok) {
        const bool ok = zok && yok[r];
        const int o = off[r];
        float2 p = make_float2(0.f, 0.f), t = make_float2(0.f, 0.f);
        if (ok) {
            p = __ldg((const float2*)(pb + o));
            t = __ldg((const float2*)(tb + o));
        }
        nP[r] = pk2(p.x, p.y);
        nT[r] = pk2(t.x, t.y);
        nE[r][0] = 0.f; nE[r][1] = 0.f; nE[r][2] = 0.f; nE[r][3] = 0.f;
        if (hasL && ok) { nE[r][0] = __ldg(pb + o - 1); nE[r][2] = __ldg(tb + o - 1); }
        if (hasR && ok) { nE[r][1] = __ldg(pb + o + 2); nE[r][3] = __ldg(tb + o + 2); }
    };

    {
        const bool zok0 = ((unsigned)zp < DIM);
        load_row(0, zok0);
        load_row(1, zok0);
    }

    for (int it = 0; it <= 26; ++it) {
        // latch current plane
        u64 cP[2] = { nP[0], nP[1] }, cT[2] = { nT[0], nT[1] };
        float cE[2][4];
#pragma unroll
        for (int r = 0; r < 2; ++r)
#pragma unroll
            for (int e = 0; e < 4; ++e) cE[r][e] = nE[r][e];

        // prefetch next plane
        if (it < 26) {
            zp++;
            off[0] += PLANE; off[1] += PLANE;
            const bool zok = ((unsigned)zp < DIM);
            load_row(0, zok);
            load_row(1, zok);
        }

        // ---- per-row x-window sums + z-ring ----
        u64 zs[2][5];
#pragma unroll
        for (int r = 0; r < 2; ++r) {
            float p1, p2, t1, t2;
            upk2(cP[r], p1, p2); upk2(cT[r], t1, t2);
            float p0 = __shfl_up_sync(0xffffffffu, p2, 1);
            float p3 = __shfl_down_sync(0xffffffffu, p1, 1);
            float t0 = __shfl_up_sync(0xffffffffu, t2, 1);
            float t3 = __shfl_down_sync(0xffffffffu, t1, 1);
            if (lx) { p0 = cE[r][0]; t0 = cE[r][2]; }
            if (rx) { p3 = cE[r][1]; t3 = cE[r][3]; }

            const u64 A = pk2(p0, p1), M = cP[r], B = pk2(p2, p3);
            const u64 C = pk2(t0, t1), N = cT[r], D = pk2(t2, t3);

            u64 xs[5];
            xs[0] = f2add(f2add(A, M), B);
            xs[1] = f2add(f2add(C, N), D);
            xs[2] = f2fma(A, A, f2fma(M, M, f2mul(B, B)));
            xs[3] = f2fma(C, C, f2fma(N, N, f2mul(D, D)));
            xs[4] = f2fma(A, C, f2fma(M, N, f2mul(B, D)));

#pragma unroll
            for (int q = 0; q < 5; ++q) {
                zs[r][q] = f2add(rP[r][q], xs[q]);
                rP[r][q] = f2add(rA[r][q], xs[q]);
                rA[r][q] = xs[q];
            }
        }

        if (it >= 3) {   // block-uniform; output plane z = zc - 3 + it
            const int p = it & 1;
#pragma unroll
            for (int q = 0; q < 5; ++q) {
                s[p][q][0][ty][tx] = zs[0][q];
                s[p][q][1][ty][tx] = zs[1][q];
            }
            __syncthreads();

            // output at row a: needs b(ty-1) [smem] and own b [reg]
            if (ty >= 1) {
                u64 S[5];
#pragma unroll
                for (int q = 0; q < 5; ++q)
                    S[q] = f2add(zs[0][q], f2add(s[p][q][1][ty - 1][tx], zs[1][q]));
                const u64 SIm = f2mul(S[0], NEGC);
                const u64 SJm = f2mul(S[1], NEGC);
                const u64 cr  = f2fma(SIm, S[1], S[4]);
                const u64 pv  = f2fma(SIm, S[0], S[2]);
                const u64 tv  = f2fma(SJm, S[1], S[3]);
                const u64 num = f2mul(cr, cr);
                const u64 den = f2fma(tv, pv, DRP);
                float n0, n1, d0, d1;
                upk2(num, n0, n1); upk2(den, d0, d1);
                acc += __fdividef(n0, d0) + __fdividef(n1, d1);
            }
            // output at row b: needs own a [reg] and a(ty+1) [smem]
            if (ty <= BYT - 2) {
                u64 S[5];
#pragma unroll
                for (int q = 0; q < 5; ++q)
                    S[q] = f2add(zs[1][q], f2add(zs[0][q], s[p][q][0][ty + 1][tx]));
                const u64 SIm = f2mul(S[0], NEGC);
                const u64 SJm = f2mul(S[1], NEGC);
                const u64 cr  = f2fma(SIm, S[1], S[4]);
                const u64 pv  = f2fma(SIm, S[0], S[2]);
                const u64 tv  = f2fma(SJm, S[1], S[3]);
                const u64 num = f2mul(cr, cr);
                const u64 den = f2fma(tv, pv, DRP);
                float n0, n1, d0, d1;
                upk2(num, n0, n1); upk2(den, d0, d1);
                acc += __fdividef(n0, d0) + __fdividef(n1, d1);
            }
        }
    }

    // ---- block reduction + fused finalize ----
#pragma unroll
    for (int o = 16; o > 0; o >>= 1)
        acc += __shfl_down_sync(0xffffffffu, acc, o);

    __syncthreads();                      // done with stencil smem
    float* wsum = (float*)&s[0][0][0][0][0];
    const int tid = ty * BXT + tx;
    const int wid = tid >> 5;             // 9 warps
    if ((tid & 31) == 0) wsum[wid] = acc;
    __syncthreads();

    if (tid == 0) {
        float blocksum = 0.f;
#pragma unroll
        for (int w = 0; w < NTHR / 32; ++w) blocksum += wsum[w];
        atomicAdd(&g_acc, (double)blocksum);
        __threadfence();
        unsigned t = atomicAdd(&g_count, 1u);
        if (t == NBLK - 1) {              // last block: finalize + reset for replay
            double total = *((volatile double*)&g_acc);
            out[0] = (float)(-total / N_TOTAL);
            g_acc = 0.0;
            g_count = 0u;
        }
    }
}

extern "C" void kernel_launch(void* const* d_in, const int* in_sizes, int n_in,
                              void* d_out, int out_size) {
    const float* pred = (const float*)d_in[0];
    const float* targ = (const float*)d_in[1];
    float* out = (float*)d_out;

    dim3 block(BXT, BYT);
    dim3 grid(GX, GY, GZ);
    ncc_kernel<<<grid, block>>>(pred, targ, out);
}